// round 8
// baseline (speedup 1.0000x reference)
#include <cuda_runtime.h>
#include <cuda_bf16.h>
#include <cstdint>

// Problem constants
#define B_  256
#define L_  500
#define E_  300
#define H_  10
#define K_  5

#define NT    512
#define NKS   19          // k-steps of 16 (covers 304, valid 300)
#define NNT   7           // n-tiles of 8 (56 cols, valid 50)
#define NST   3           // A pipeline stages

#define ROWF    20                     // floats per staged row (16 + 4 pad; 80 B, 16B-aligned)
#define STAGEF  (NT * ROWF)            // 10240 floats per stage
#define STAGEB  (STAGEF * 4)           // 40960 B

// shared memory layout (bytes)
#define SM_A     0                               // 3 stages = 122880
#define SM_BHI   (NST * STAGEB)                  // 122880
#define SM_BLO   (SM_BHI + NKS*NNT*64*4)         // 156928
#define SM_AE    (SM_BLO + NKS*NNT*64*4)         // 190976
#define SMEM_BYTES (SM_AE + 640)                 // 191616
// post-mainloop aliases (A stages + nothing else needed): proj 100000 B, scores 10000 B
#define SM_PROJ  0
#define SM_SC    (50 * L_ * 4)                   // 100000

__device__ __forceinline__ uint32_t cvt_bf2(float lo, float hi) {
    uint32_t d;
    asm("cvt.rn.bf16x2.f32 %0, %1, %2;" : "=r"(d) : "f"(hi), "f"(lo));
    return d;
}
__device__ __forceinline__ uint32_t cvt_bf2_lo(float2 v, uint32_t hi) {
    float h0 = __uint_as_float(hi << 16);
    float h1 = __uint_as_float(hi & 0xFFFF0000u);
    return cvt_bf2(v.x - h0, v.y - h1);
}

__device__ __forceinline__ void mma_bf16(float* d, const uint32_t* a,
                                         uint32_t b0, uint32_t b1) {
    asm volatile(
        "mma.sync.aligned.m16n8k16.row.col.f32.bf16.bf16.f32 "
        "{%0,%1,%2,%3}, {%4,%5,%6,%7}, {%8,%9}, {%0,%1,%2,%3};"
        : "+f"(d[0]), "+f"(d[1]), "+f"(d[2]), "+f"(d[3])
        : "r"(a[0]), "r"(a[1]), "r"(a[2]), "r"(a[3]), "r"(b0), "r"(b1));
}

__global__ __launch_bounds__(NT, 1)
void anr_arl_kernel(const float* __restrict__ review,
                    const float* __restrict__ aspProj,
                    const float* __restrict__ aspEmbed,
                    float* __restrict__ out)
{
    extern __shared__ char smc[];
    float*    sA     = reinterpret_cast<float*>(smc + SM_A);      // 3-stage A tiles
    uint32_t* sBhi   = reinterpret_cast<uint32_t*>(smc + SM_BHI);
    uint32_t* sBlo   = reinterpret_cast<uint32_t*>(smc + SM_BLO);
    float*    sAE    = reinterpret_cast<float*>(smc + SM_AE);
    float*    sProj  = reinterpret_cast<float*>(smc + SM_PROJ);   // alias A (post-mainloop)
    float*    sScores= reinterpret_cast<float*>(smc + SM_SC);     // alias A (post-mainloop)

    const int tid  = threadIdx.x;
    const int wid  = tid >> 5, lane = tid & 31;
    const int b    = blockIdx.x;
    const float* revB = review + (size_t)b * (L_ * E_);
    const unsigned aBase = (unsigned)__cvta_generic_to_shared(sA);

    // ---- stage B fragments: [ks][nt][r][lane] u32 = bf16 pair (k0, k0+1) ----
    for (int idx = tid; idx < NKS * NNT * 64; idx += NT) {
        int lan = idx & 31;
        int r   = (idx >> 5) & 1;
        int nt  = (idx >> 6) % NNT;
        int ks  = idx / (NNT * 64);
        int k0  = ks * 16 + ((lan & 3) << 1) + r * 8;
        int n   = nt * 8 + (lan >> 2);
        float w0 = 0.f, w1 = 0.f;
        if (n < 50) {
            int base = (n / H_) * (E_ * H_) + (n % H_);
            if (k0 < E_)     w0 = aspProj[base + k0 * H_];
            if (k0 + 1 < E_) w1 = aspProj[base + (k0 + 1) * H_];
        }
        uint32_t hi = cvt_bf2(w0, w1);
        float h0 = __uint_as_float(hi << 16);
        float h1 = __uint_as_float(hi & 0xFFFF0000u);
        uint32_t lo = cvt_bf2(w0 - h0, w1 - h1);
        sBhi[idx] = hi;
        sBlo[idx] = lo;
    }
    for (int i = tid; i < K_ * 3 * H_; i += NT) sAE[i] = aspEmbed[i];

    // ---- A staging: stage ks = all 512 rows x 16 cols fp32 via cp.async.cg 16B ----
    auto stageA = [&](int ks) {
        const unsigned dbase = aBase + (unsigned)(ks % NST) * (unsigned)STAGEB;
        const char* src = reinterpret_cast<const char*>(revB) + (size_t)ks * 64;
#pragma unroll
        for (int i = 0; i < 4; i++) {
            int c = tid + i * NT;                 // 0..2047
            int row = c >> 2, part = c & 3;
            unsigned d = dbase + (unsigned)row * 80u + (unsigned)part * 16u;
            int col0 = ks * 16 + part * 4;
            if (col0 >= E_) {
                // zero-pad k-columns >= 300 (these feed VALID output rows)
                asm volatile("st.shared.v4.b32 [%0], {%1,%1,%1,%1};"
                             :: "r"(d), "r"(0) : "memory");
            } else if (row < L_) {
                const char* s = src + (size_t)row * (E_ * 4) + part * 16;
                asm volatile("cp.async.cg.shared.global [%0], [%1], 16;"
                             :: "r"(d), "l"(s) : "memory");
            }
            // rows >= 500: leave garbage; their outputs are discarded
        }
        asm volatile("cp.async.commit_group;" ::: "memory");
    };

    stageA(0);
    stageA(1);

    // ---- GEMM mainloop ----
    float acc[2][NNT][4];
#pragma unroll
    for (int t = 0; t < 2; t++)
#pragma unroll
        for (int nt = 0; nt < NNT; nt++)
#pragma unroll
            for (int c = 0; c < 4; c++) acc[t][nt][c] = 0.f;

    const int mrow0 = wid * 32;
    const int rquad = lane >> 2;          // 0..7
    const int cpair = (lane & 3) << 1;    // 0,2,4,6

#pragma unroll 1
    for (int ks = 0; ks < NKS; ks++) {
        if (ks + 2 < NKS) asm volatile("cp.async.wait_group 1;" ::: "memory");
        else              asm volatile("cp.async.wait_group 0;" ::: "memory");
        __syncthreads();
        if (ks + 2 < NKS) stageA(ks + 2);   // refill the buffer freed last iteration

        const float* ab = sA + (ks % NST) * STAGEF;
        uint32_t ah[2][4], al[2][4];
#pragma unroll
        for (int t = 0; t < 2; t++) {
            int r0 = mrow0 + t * 16 + rquad;
            float2 v00 = *reinterpret_cast<const float2*>(ab + r0 * ROWF + cpair);
            float2 v10 = *reinterpret_cast<const float2*>(ab + (r0 + 8) * ROWF + cpair);
            float2 v01 = *reinterpret_cast<const float2*>(ab + r0 * ROWF + cpair + 8);
            float2 v11 = *reinterpret_cast<const float2*>(ab + (r0 + 8) * ROWF + cpair + 8);
            ah[t][0] = cvt_bf2(v00.x, v00.y);  al[t][0] = cvt_bf2_lo(v00, ah[t][0]);
            ah[t][1] = cvt_bf2(v10.x, v10.y);  al[t][1] = cvt_bf2_lo(v10, ah[t][1]);
            ah[t][2] = cvt_bf2(v01.x, v01.y);  al[t][2] = cvt_bf2_lo(v01, ah[t][2]);
            ah[t][3] = cvt_bf2(v11.x, v11.y);  al[t][3] = cvt_bf2_lo(v11, ah[t][3]);
        }

        const uint32_t* bh = sBhi + ks * (NNT * 64);
        const uint32_t* bl = sBlo + ks * (NNT * 64);
#pragma unroll
        for (int nt = 0; nt < NNT; nt++) {
            uint32_t b0h = bh[(nt * 2 + 0) * 32 + lane];
            uint32_t b1h = bh[(nt * 2 + 1) * 32 + lane];
            uint32_t b0l = bl[(nt * 2 + 0) * 32 + lane];
            uint32_t b1l = bl[(nt * 2 + 1) * 32 + lane];
#pragma unroll
            for (int t = 0; t < 2; t++) {
                mma_bf16(acc[t][nt], ah[t], b0h, b1h);   // hi*hi
                mma_bf16(acc[t][nt], ah[t], b0l, b1l);   // hi*lo
                mma_bf16(acc[t][nt], al[t], b0h, b1h);   // lo*hi
            }
        }
    }
    __syncthreads();   // A stages dead; sProj/sScores alias them from here on

    // ---- writeback acc -> sProj[kh][l] ----
#pragma unroll
    for (int t = 0; t < 2; t++) {
#pragma unroll
        for (int nt = 0; nt < NNT; nt++) {
#pragma unroll
            for (int c = 0; c < 4; c++) {
                int row = mrow0 + t * 16 + rquad + ((c >> 1) ? 8 : 0);
                int col = nt * 8 + cpair + (c & 1);
                if (row < L_ && col < 50)
                    sProj[col * L_ + row] = acc[t][nt][c];
            }
        }
    }
    __syncthreads();

    // ---- window-3 attention scores: scores[k][l] ----
    for (int idx = tid; idx < K_ * L_; idx += NT) {
        int k = idx / L_, l = idx - k * L_;
        const float* aEk = sAE + k * 3 * H_;
        const float* pk  = sProj + k * H_ * L_;
        float s = 0.f;
#pragma unroll
        for (int i = 0; i < 3; i++) {
            int ll = l - 1 + i;
            if ((unsigned)ll < (unsigned)L_) {
#pragma unroll
                for (int h = 0; h < H_; h++)
                    s += pk[h * L_ + ll] * aEk[h * 3 + i];
            }
        }
        sScores[idx] = s;
    }
    __syncthreads();

    // ---- softmax over l per k (warp k), write attn out (B,K,L) ----
    if (wid < K_) {
        float* srow = sScores + wid * L_;
        float m = -3.402823466e38f;
        for (int l = lane; l < L_; l += 32) m = fmaxf(m, srow[l]);
#pragma unroll
        for (int o = 16; o > 0; o >>= 1) m = fmaxf(m, __shfl_xor_sync(0xffffffffu, m, o));
        float ssum = 0.f;
        for (int l = lane; l < L_; l += 32) {
            float ev = expf(srow[l] - m);
            srow[l] = ev;
            ssum += ev;
        }
#pragma unroll
        for (int o = 16; o > 0; o >>= 1) ssum += __shfl_xor_sync(0xffffffffu, ssum, o);
        float inv = 1.0f / ssum;
        float* oa = out + (size_t)b * (K_ * L_) + wid * L_;
        for (int l = lane; l < L_; l += 32) {
            float a = srow[l] * inv;
            srow[l] = a;          // keep normalized attn for pooling
            oa[l] = a;
        }
    }
    __syncthreads();

    // ---- pooled rep: rep[k][h] = sum_l proj[kh][l] * attn[k][l]  -> (B,K,H) ----
    float* orep = out + (size_t)B_ * K_ * L_ + (size_t)b * (K_ * H_);
    for (int kh = wid; kh < K_ * H_; kh += (NT / 32)) {
        int k = kh / H_;
        const float* pk = sProj + kh * L_;
        const float* ak = sScores + k * L_;
        float s = 0.f;
        for (int l = lane; l < L_; l += 32) s += pk[l] * ak[l];
#pragma unroll
        for (int o = 16; o > 0; o >>= 1) s += __shfl_xor_sync(0xffffffffu, s, o);
        if (lane == 0) orep[kh] = s;
    }
}

extern "C" void kernel_launch(void* const* d_in, const int* in_sizes, int n_in,
                              void* d_out, int out_size)
{
    const float* review   = (const float*)d_in[0];
    const float* aspProj  = (const float*)d_in[1];
    const float* aspEmbed = (const float*)d_in[2];
    float* out = (float*)d_out;

    cudaFuncSetAttribute(anr_arl_kernel,
                         cudaFuncAttributeMaxDynamicSharedMemorySize, SMEM_BYTES);
    anr_arl_kernel<<<B_, NT, SMEM_BYTES>>>(review, aspProj, aspEmbed, out);
}